// round 9
// baseline (speedup 1.0000x reference)
#include <cuda_runtime.h>
#include <cuda_bf16.h>
#include <cstdint>

#define BB 8
#define TT 1024
#define HH 128
#define LL 64      // mLSTM chunk length
#define NC 16      // TT / LL

// ---------------- static device scratch (no allocation APIs) ---------------
__device__ float g_Wx[BB * TT * 512];     // sLSTM input projections (+sb), plain layout
__device__ float g_h1[BB * TT * HH];      // sLSTM output sequence
__device__ float g_proj[BB * TT * 768];   // mLSTM projections [q k v i f o]
__device__ float g_PM[BB * TT * HH];      // prefix-max of u within chunk
__device__ float g_Vt[BB * TT * HH];      // v * e^u
__device__ float g_P[BB * TT * HH];       // prefix-sum of k * e^u
__device__ float g_G[BB * TT * HH];       // intra-chunk numerator (pre e^{-M})
__device__ float g_Gc[BB * NC * HH * HH]; // per-chunk  Vt^T K
__device__ float g_Cst[BB * NC * HH * HH];// C state at each chunk start
__device__ float g_aL[BB * NC * HH];      // chunk-final cumsum(f)
__device__ float g_m0s[BB * NC * HH];     // m at chunk start
__device__ float g_n0s[BB * NC * HH];     // n at chunk start
__device__ float g_rden[BB * TT];         // 1 / denom

static __device__ __forceinline__ unsigned su32(const void* p) {
    return (unsigned)__cvta_generic_to_shared(p);
}

// ---- f32x2 packed helpers (sm_100+) ----
static __device__ __forceinline__ unsigned long long pack2(float a, float b) {
    unsigned long long r;
    asm("mov.b64 %0, {%1, %2};" : "=l"(r) : "f"(a), "f"(b));
    return r;
}
static __device__ __forceinline__ void fma2(unsigned long long& d,
                                            unsigned long long a,
                                            unsigned long long b) {
    asm("fma.rn.f32x2 %0, %1, %2, %0;" : "+l"(d) : "l"(a), "l"(b));
}
static __device__ __forceinline__ float2 unpack2(unsigned long long v) {
    float2 f;
    asm("mov.b64 {%0, %1}, %2;" : "=f"(f.x), "=f"(f.y) : "l"(v));
    return f;
}
static __device__ __forceinline__ float tanh_fast(float x) {
    float r;
    asm("tanh.approx.f32 %0, %1;" : "=f"(r) : "f"(x));
    return r;
}

extern __shared__ float dsm[];

// ===========================================================================
// GEMM: Out[m][n] = (sum_k X[m][k]*Wseg[nloc][k] + Bseg[nloc]) * scale[seg]
// ===========================================================================
struct GemmArgs {
    const float* W[6];
    const float* Bi[6];
    float scale[6];
    int sigm[6];
};

__global__ __launch_bounds__(256) void gemm_k(int mode, const float* __restrict__ Xp, GemmArgs a)
{
    const int K = 128;
    const int Ntot = (mode == 0) ? 512 : 768;
    const float* __restrict__ X = (mode == 0) ? Xp : g_h1;
    float* __restrict__ Out = (mode == 0) ? g_Wx : g_proj;

    __shared__ float Xs[64][68];
    __shared__ float Ws[64][68];

    const int bm = blockIdx.y * 64;
    const int bn = blockIdx.x * 64;
    const int seg = bn >> 7;
    const int nl0 = bn & 127;
    const float* __restrict__ W = a.W[seg];
    const int tid = threadIdx.x;

    const int tx = tid & 15, ty = tid >> 4;
    unsigned long long acc2[4][2];
#pragma unroll
    for (int i = 0; i < 4; i++) { acc2[i][0] = 0ull; acc2[i][1] = 0ull; }

    const int c4 = tid & 15;
    const int r0 = tid >> 4;

    for (int k0 = 0; k0 < K; k0 += 64) {
        __syncthreads();
#pragma unroll
        for (int rr = r0; rr < 64; rr += 16) {
            float4 xv = *(const float4*)&X[(size_t)(bm + rr) * K + k0 + c4 * 4];
            Xs[c4 * 4 + 0][rr] = xv.x; Xs[c4 * 4 + 1][rr] = xv.y;
            Xs[c4 * 4 + 2][rr] = xv.z; Xs[c4 * 4 + 3][rr] = xv.w;
            float4 wv = *(const float4*)&W[(size_t)(nl0 + rr) * K + k0 + c4 * 4];
            Ws[c4 * 4 + 0][rr] = wv.x; Ws[c4 * 4 + 1][rr] = wv.y;
            Ws[c4 * 4 + 2][rr] = wv.z; Ws[c4 * 4 + 3][rr] = wv.w;
        }
        __syncthreads();
#pragma unroll 4
        for (int k = 0; k < 64; k++) {
            float4 xm = *(const float4*)&Xs[k][ty * 4];
            ulonglong2 wn2 = *(const ulonglong2*)&Ws[k][tx * 4];
            unsigned long long xr[4] = {pack2(xm.x, xm.x), pack2(xm.y, xm.y),
                                        pack2(xm.z, xm.z), pack2(xm.w, xm.w)};
#pragma unroll
            for (int i = 0; i < 4; i++) {
                fma2(acc2[i][0], xr[i], wn2.x);
                fma2(acc2[i][1], xr[i], wn2.y);
            }
        }
    }

    const float sc = a.scale[seg];
    const int sg = a.sigm[seg];
    const float* __restrict__ Bp = a.Bi[seg];
#pragma unroll
    for (int i = 0; i < 4; i++) {
        int m = bm + ty * 4 + i;
        float2 p0 = unpack2(acc2[i][0]);
        float2 p1 = unpack2(acc2[i][1]);
        float av[4] = {p0.x, p0.y, p1.x, p1.y};
#pragma unroll
        for (int j = 0; j < 4; j++) {
            int n = bn + tx * 4 + j;
            float v = (av[j] + Bp[nl0 + tx * 4 + j]) * sc;
            if (sg) v = 1.f / (1.f + __expf(-v));
            Out[(size_t)m * Ntot + n] = v;
        }
    }
}

// ===========================================================================
// sLSTM scan: 4 clusters x 4 CTAs, TWO batches interleaved per cluster.
// GATE-SLICE mapping: CTA rank computes gate `rank` for ALL 128 units and
// broadcasts its 128 gate pre-activations; every CTA then redundantly runs
// the full nonlinear update (state replicated, deterministic). h stays local.
// 256 threads: half-row per thread (32 u64 weight regs), pair-combine by shfl.
// ===========================================================================
__global__ void __cluster_dims__(4, 1, 1) __launch_bounds__(256, 1)
slstm_k(const float* __restrict__ sR)
{
    __shared__ __align__(16) float h_sA[HH];
    __shared__ __align__(16) float h_sB[HH];
    __shared__ __align__(16) float gbA[2][4][HH];   // [buf][gate][unit]
    __shared__ __align__(16) float gbB[2][4][HH];
    __shared__ __align__(8) unsigned long long mbA, mbB;

    const int tid = threadIdx.x;
    const unsigned rank = (unsigned)(blockIdx.x & 3);
    const int cid = blockIdx.x >> 2;            // cluster 0..3
    const int bA = cid * 2, bB = cid * 2 + 1;
    const int wrp = tid >> 5;                   // 0..7
    const int lan = tid & 31;
    const int rloc = wrp * 16 + (lan >> 1);     // unit / local row 0..127
    const int kh = lan & 1;                     // k-half
    const int grow = (int)rank * 128 + rloc;    // fused weight row (gate=rank)

    // --- this thread's half-row of recurrent weights: 64 f32 = 32 f32x2 ---
    unsigned long long w2[32];
    {
        const float4* wr = (const float4*)(sR + (size_t)grow * 128 + kh * 64);
#pragma unroll
        for (int k4 = 0; k4 < 16; k4++) {
            float4 v = wr[k4];
            w2[2 * k4 + 0] = pack2(v.x, v.y);
            w2[2 * k4 + 1] = pack2(v.z, v.w);
        }
    }
    if (tid < HH) { h_sA[tid] = 0.f; h_sB[tid] = 0.f; }
    if (tid == 0) {
        asm volatile("mbarrier.init.shared.b64 [%0], %1;" :: "r"(su32(&mbA)), "r"(512) : "memory");
        asm volatile("mbarrier.init.shared.b64 [%0], %1;" :: "r"(su32(&mbB)), "r"(512) : "memory");
    }
    __syncthreads();
    asm volatile("barrier.cluster.arrive;\n\tbarrier.cluster.wait;\n" ::: "memory");

    // each lane serves 2 destination CTAs (kh=0 -> {0,1}, kh=1 -> {2,3})
    const unsigned d0 = 2u * (unsigned)kh, d1 = d0 + 1u;
    const unsigned slotOff = (unsigned)((rank * 128 + rloc) * 4);  // within gbuf[buf]
    const unsigned barA_l = su32(&mbA), barB_l = su32(&mbB);
    unsigned gA0, gA1, gB0, gB1, bA0, bA1, bB0, bB1;
    {
        unsigned gAbase = su32(&gbA[0][0][0]);
        unsigned gBbase = su32(&gbB[0][0][0]);
        asm("mapa.shared::cluster.u32 %0, %1, %2;" : "=r"(gA0) : "r"(gAbase), "r"(d0));
        asm("mapa.shared::cluster.u32 %0, %1, %2;" : "=r"(gA1) : "r"(gAbase), "r"(d1));
        asm("mapa.shared::cluster.u32 %0, %1, %2;" : "=r"(gB0) : "r"(gBbase), "r"(d0));
        asm("mapa.shared::cluster.u32 %0, %1, %2;" : "=r"(gB1) : "r"(gBbase), "r"(d1));
        asm("mapa.shared::cluster.u32 %0, %1, %2;" : "=r"(bA0) : "r"(barA_l), "r"(d0));
        asm("mapa.shared::cluster.u32 %0, %1, %2;" : "=r"(bA1) : "r"(barA_l), "r"(d1));
        asm("mapa.shared::cluster.u32 %0, %1, %2;" : "=r"(bB0) : "r"(barB_l), "r"(d0));
        asm("mapa.shared::cluster.u32 %0, %1, %2;" : "=r"(bB1) : "r"(barB_l), "r"(d1));
        gA0 += slotOff; gA1 += slotOff; gB0 += slotOff; gB1 += slotOff;
    }

    // replicated per-unit state (meaningful for tid < 128; unit = tid)
    float cA = 0.f, nA = 0.f, mA = 0.f;
    float cB = 0.f, nB = 0.f, mB = 0.f;
    const float* __restrict__ wxA = g_Wx + (size_t)bA * TT * 512 + grow;
    const float* __restrict__ wxB = g_Wx + (size_t)bB * TT * 512 + grow;
    float* __restrict__ h1A = g_h1 + (size_t)bA * TT * HH;
    float* __restrict__ h1B = g_h1 + (size_t)bB * TT * HH;

    float wxA_cur = wxA[0];
    float wxB_cur = wxB[0];

    for (int t = 0; t < TT; t++) {
        const unsigned buf = (unsigned)(t & 1);
        const unsigned bufByte = buf * 2048u;       // gbuf[buf] stride in bytes
        const unsigned par = (unsigned)(t & 1);
        float wxA_nxt = (t + 1 < TT) ? wxA[(size_t)(t + 1) * 512] : 0.f;
        float wxB_nxt = (t + 1 < TT) ? wxB[(size_t)(t + 1) * 512] : 0.f;

        // ---- matvec A over local h_sA (half-row), pair-combine, broadcast ----
        {
            unsigned long long a0 = 0ull, a1 = 0ull, a2 = 0ull, a3 = 0ull;
            const ulonglong2* h2 = (const ulonglong2*)(h_sA + kh * 64);
#pragma unroll
            for (int k = 0; k < 8; k++) {
                ulonglong2 p = h2[2 * k];
                ulonglong2 q = h2[2 * k + 1];
                fma2(a0, w2[4 * k + 0], p.x);
                fma2(a1, w2[4 * k + 1], p.y);
                fma2(a2, w2[4 * k + 2], q.x);
                fma2(a3, w2[4 * k + 3], q.y);
            }
            float2 f0 = unpack2(a0), f1 = unpack2(a1), f2 = unpack2(a2), f3 = unpack2(a3);
            float part = ((f0.x + f0.y) + (f1.x + f1.y)) + ((f2.x + f2.y) + (f3.x + f3.y));
            part += __shfl_xor_sync(0xffffffffu, part, 1);
            float g = part + wxA_cur;
            asm volatile("st.shared::cluster.f32 [%0], %1;" :: "r"(gA0 + bufByte), "f"(g) : "memory");
            asm volatile("st.shared::cluster.f32 [%0], %1;" :: "r"(gA1 + bufByte), "f"(g) : "memory");
            asm volatile("mbarrier.arrive.release.cluster.shared::cluster.b64 _, [%0];" :: "r"(bA0) : "memory");
            asm volatile("mbarrier.arrive.release.cluster.shared::cluster.b64 _, [%0];" :: "r"(bA1) : "memory");
        }

        // ---- matvec B ----
        {
            unsigned long long a0 = 0ull, a1 = 0ull, a2 = 0ull, a3 = 0ull;
            const ulonglong2* h2 = (const ulonglong2*)(h_sB + kh * 64);
#pragma unroll
            for (int k = 0; k < 8; k++) {
                ulonglong2 p = h2[2 * k];
                ulonglong2 q = h2[2 * k + 1];
                fma2(a0, w2[4 * k + 0], p.x);
                fma2(a1, w2[4 * k + 1], p.y);
                fma2(a2, w2[4 * k + 2], q.x);
                fma2(a3, w2[4 * k + 3], q.y);
            }
            float2 f0 = unpack2(a0), f1 = unpack2(a1), f2 = unpack2(a2), f3 = unpack2(a3);
            float part = ((f0.x + f0.y) + (f1.x + f1.y)) + ((f2.x + f2.y) + (f3.x + f3.y));
            part += __shfl_xor_sync(0xffffffffu, part, 1);
            float g = part + wxB_cur;
            asm volatile("st.shared::cluster.f32 [%0], %1;" :: "r"(gB0 + bufByte), "f"(g) : "memory");
            asm volatile("st.shared::cluster.f32 [%0], %1;" :: "r"(gB1 + bufByte), "f"(g) : "memory");
            asm volatile("mbarrier.arrive.release.cluster.shared::cluster.b64 _, [%0];" :: "r"(bB0) : "memory");
            asm volatile("mbarrier.arrive.release.cluster.shared::cluster.b64 _, [%0];" :: "r"(bB1) : "memory");
        }

        // ---- wait A, nonlinear update A (redundant across CTAs; unit = tid) ----
        asm volatile(
            "{\n\t.reg .pred P;\n\t"
            "WA%=:\n\t"
            "mbarrier.try_wait.parity.acquire.cluster.shared::cta.b64 P, [%0], %1, 0x989680;\n\t"
            "@P bra.uni DA%=;\n\tbra.uni WA%=;\n\tDA%=:\n\t}"
            :: "r"(barA_l), "r"(par) : "memory");
        if (tid < HH) {
            float gi = gbA[buf][0][tid], gf = gbA[buf][1][tid];
            float gz = gbA[buf][2][tid], go = gbA[buf][3][tid];
            float mn = fmaxf(gf + mA, gi);
            float ii = __expf(gi - mn);
            float ff = __expf(gf + mA - mn);
            cA = ff * cA + ii * tanh_fast(gz);
            nA = ff * nA + ii;
            mA = mn;
            float sg = __fdividef(1.f, 1.f + __expf(-go));
            float hn = __fdividef(cA, nA) * sg;
            h_sA[tid] = hn;
            h1A[(size_t)t * HH + tid] = hn;
        }

        // ---- wait B, nonlinear update B ----
        asm volatile(
            "{\n\t.reg .pred P;\n\t"
            "WB%=:\n\t"
            "mbarrier.try_wait.parity.acquire.cluster.shared::cta.b64 P, [%0], %1, 0x989680;\n\t"
            "@P bra.uni DB%=;\n\tbra.uni WB%=;\n\tDB%=:\n\t}"
            :: "r"(barB_l), "r"(par) : "memory");
        if (tid < HH) {
            float gi = gbB[buf][0][tid], gf = gbB[buf][1][tid];
            float gz = gbB[buf][2][tid], go = gbB[buf][3][tid];
            float mn = fmaxf(gf + mB, gi);
            float ii = __expf(gi - mn);
            float ff = __expf(gf + mB - mn);
            cB = ff * cB + ii * tanh_fast(gz);
            nB = ff * nB + ii;
            mB = mn;
            float sg = __fdividef(1.f, 1.f + __expf(-go));
            float hn = __fdividef(cB, nB) * sg;
            h_sB[tid] = hn;
            h1B[(size_t)t * HH + tid] = hn;
        }

        __syncthreads();   // h_sA/h_sB updated before next matvec reads
        wxA_cur = wxA_nxt;
        wxB_cur = wxB_nxt;
    }

    asm volatile("barrier.cluster.arrive;\n\tbarrier.cluster.wait;\n" ::: "memory");
}

// ===========================================================================
// mLSTM chunkwise-parallel pipeline (unchanged from R8)
// ===========================================================================

__global__ __launch_bounds__(128) void prep_k()
{
    const int b = blockIdx.x >> 4;
    const int c = blockIdx.x & 15;
    const int j = threadIdx.x;
    const float* __restrict__ base = g_proj + ((size_t)(b * TT + c * LL) * 768) + j;
    float a = 0.f, pm = -1e30f, p = 0.f;
    size_t oidx = (size_t)(b * TT + c * LL) * HH + j;

    float fb[2][4], ib[2][4], vb[2][4], kb[2][4];
#pragma unroll
    for (int s = 0; s < 4; s++) {
        const float* row = base + (size_t)s * 768;
        fb[0][s] = row[512]; ib[0][s] = row[384];
        vb[0][s] = row[256]; kb[0][s] = row[128];
    }
    for (int gidx = 0; gidx < 16; gidx++) {
        const int cb = gidx & 1;
        if (gidx + 1 < 16) {
            const float* gbase = base + (size_t)(gidx + 1) * 4 * 768;
#pragma unroll
            for (int s = 0; s < 4; s++) {
                const float* row = gbase + (size_t)s * 768;
                fb[cb ^ 1][s] = row[512]; ib[cb ^ 1][s] = row[384];
                vb[cb ^ 1][s] = row[256]; kb[cb ^ 1][s] = row[128];
            }
        }
#pragma unroll
        for (int s = 0; s < 4; s++) {
            a += fb[cb][s];
            float u = ib[cb][s] - a;
            pm = fmaxf(pm, u);
            float eu = __expf(u);
            g_PM[oidx] = pm;
            g_Vt[oidx] = vb[cb][s] * eu;
            p = fmaf(kb[cb][s], eu, p);
            g_P[oidx] = p;
            oidx += HH;
        }
    }
    g_aL[(b * NC + c) * HH + j] = a;
}

__global__ __launch_bounds__(128) void n0m0_k()
{
    const int b = blockIdx.x;
    const int j = threadIdx.x;
    float m0 = 0.f, n0 = 0.f;
    for (int c = 0; c < NC; c++) {
        int ci = (b * NC + c) * HH + j;
        g_m0s[ci] = m0;
        g_n0s[ci] = n0;
        size_t li = (size_t)(b * TT + c * LL + (LL - 1)) * HH + j;
        float pml = g_PM[li];
        float pl  = g_P[li];
        float ML = fmaxf(m0, pml);
        n0 = __expf(m0 - ML) * n0 + __expf(-ML) * pl;
        m0 = g_aL[ci] + ML;
    }
}

// ---- fused: S = QK^T (masked), G = S*Vt, Gc = Vt^T K   per (b,c)
__global__ __launch_bounds__(256) void sg_k()
{
    float* Qs = dsm;                                   // 8192
    float* Ks = dsm + 8192;                            // 8448
    float* Vs = dsm + 8192 + 8448;                     // 8448
    float* Ss = dsm + 8192 + 8448 + 8448;              // 4160
    const int b = blockIdx.x >> 4, c = blockIdx.x & 15;
    const int tid = threadIdx.x;
    const float* __restrict__ pb = g_proj + (size_t)(b * TT + c * LL) * 768;
    const float* __restrict__ vb = g_Vt + (size_t)(b * TT + c * LL) * HH;
    for (int i = tid; i < 2048; i += 256) {
        int s = i >> 5, j4 = i & 31;
        *(float4*)(Qs + s * 128 + j4 * 4) = *(const float4*)(pb + (size_t)s * 768 + j4 * 4);
        *(float4*)(Ks + s * 132 + j4 * 4) = *(const float4*)(pb + (size_t)s * 768 + 128 + j4 * 4);
        *(float4*)(Vs + s * 132 + j4 * 4) = *(const float4*)(vb + (size_t)s * HH + j4 * 4);
    }
    __syncthreads();
    {
        const int t0 = (tid >> 4) * 4, s0 = (tid & 15) * 4;
        float acc[4][4];
#pragma unroll
        for (int i = 0; i < 4; i++)
#pragma unroll
            for (int s = 0; s < 4; s++) acc[i][s] = 0.f;
        for (int jj = 0; jj < 128; jj += 4) {
            float4 q[4], k[4];
#pragma unroll
            for (int i = 0; i < 4; i++) q[i] = *(float4*)(Qs + (t0 + i) * 128 + jj);
#pragma unroll
            for (int s = 0; s < 4; s++) k[s] = *(float4*)(Ks + (s0 + s) * 132 + jj);
#pragma unroll
            for (int i = 0; i < 4; i++)
#pragma unroll
                for (int s = 0; s < 4; s++)
                    acc[i][s] += q[i].x * k[s].x + q[i].y * k[s].y
                               + q[i].z * k[s].z + q[i].w * k[s].w;
        }
#pragma unroll
        for (int i = 0; i < 4; i++)
#pragma unroll
            for (int s = 0; s < 4; s++)
                Ss[(t0 + i) * 65 + s0 + s] = (s0 + s <= t0 + i) ? acc[i][s] : 0.f;
    }
    __syncthreads();
    {
        const int t0 = (tid >> 5) * 8, r0 = (tid & 31) * 4;
        float acc[8][4];
#pragma unroll
        for (int i = 0; i < 8; i++)
#pragma unroll
            for (int jj = 0; jj < 4; jj++) acc[i][jj] = 0.f;
        for (int s = 0; s < 64; s++) {
            float4 v = *(float4*)(Vs + s * 132 + r0);
#pragma unroll
            for (int i = 0; i < 8; i++) {
                float sv = Ss[(t0 + i) * 65 + s];
                acc[i][0] = fmaf(sv, v.x, acc[i][0]);
                acc[i][1] = fmaf(sv, v.y, acc[i][1]);
                acc[i][2] = fmaf(sv, v.z, acc[i][2]);
                acc[i][3] = fmaf(sv, v.w, acc[i][3]);
            }
        }
        float* gout = g_G + (size_t)(b * TT + c * LL) * HH;
#pragma unroll
        for (int i = 0; i < 8; i++) {
            float4 o4 = {acc[i][0], acc[i][1], acc[i][2], acc[i][3]};
            *(float4*)(gout + (size_t)(t0 + i) * HH + r0) = o4;
        }
    }
    {
        const int r0 = (tid >> 4) * 8, j0 = (tid & 15) * 8;
        float acc[8][8];
#pragma unroll
        for (int i = 0; i < 8; i++)
#pragma unroll
            for (int jj = 0; jj < 8; jj++) acc[i][jj] = 0.f;
        for (int s = 0; s < 64; s++) {
            float4 va = *(float4*)(Vs + s * 132 + r0);
            float4 vb4 = *(float4*)(Vs + s * 132 + r0 + 4);
            float4 ka = *(float4*)(Ks + s * 132 + j0);
            float4 kb = *(float4*)(Ks + s * 132 + j0 + 4);
            float vr[8] = {va.x, va.y, va.z, va.w, vb4.x, vb4.y, vb4.z, vb4.w};
            float kj[8] = {ka.x, ka.y, ka.z, ka.w, kb.x, kb.y, kb.z, kb.w};
#pragma unroll
            for (int i = 0; i < 8; i++)
#pragma unroll
                for (int jj = 0; jj < 8; jj++)
                    acc[i][jj] = fmaf(vr[i], kj[jj], acc[i][jj]);
        }
        float* gout = g_Gc + (size_t)(b * NC + c) * (HH * HH);
#pragma unroll
        for (int i = 0; i < 8; i++)
#pragma unroll
            for (int jj = 0; jj < 8; jj += 4) {
                float4 v = {acc[i][jj], acc[i][jj + 1], acc[i][jj + 2], acc[i][jj + 3]};
                *(float4*)(gout + (size_t)(r0 + i) * HH + j0 + jj) = v;
            }
    }
}

__global__ __launch_bounds__(256) void cscan_k()
{
    int idx = blockIdx.x * 256 + threadIdx.x;
    int b = idx >> 14;
    int rj = idx & 16383;
    int r = rj >> 7;
    float C = 0.f;
    for (int c = 0; c < NC; c++) {
        size_t so = (size_t)(b * NC + c) * 16384 + rj;
        g_Cst[so] = C;
        float m0 = g_m0s[(b * NC + c) * HH + r];
        float pml = g_PM[(size_t)(b * TT + c * LL + LL - 1) * HH + r];
        float ML = fmaxf(m0, pml);
        C = __expf(m0 - ML) * C + __expf(-ML) * g_Gc[so];
    }
}

__global__ __launch_bounds__(256) void den_k()
{
    int g = blockIdx.x * 8 + (threadIdx.x >> 5);
    int lane = threadIdx.x & 31;
    int b = g >> 10, t = g & 1023;
    int c = t >> 6;
    int j0 = lane * 4;
    const float* q = g_proj + (size_t)(b * TT + t) * 768;
    size_t gi = (size_t)(b * TT + t) * HH;
    int ci = (b * NC + c) * HH;
    float d = 0.f;
#pragma unroll
    for (int s = 0; s < 4; s++) {
        int j = j0 + s;
        float m0 = g_m0s[ci + j];
        float pm = g_PM[gi + j];
        float g1 = __expf(fminf(0.f, m0 - pm));
        float g2 = fminf(__expf(-m0), __expf(-pm));
        float nv = g1 * g_n0s[ci + j] + g2 * g_P[gi + j];
        d = fmaf(q[j], nv, d);
    }
#pragma unroll
    for (int s2 = 16; s2 >= 1; s2 >>= 1)
        d += __shfl_xor_sync(0xffffffffu, d, s2);
    if (lane == 0) g_rden[g] = 1.f / fmaxf(fabsf(d), 1.f);
}

__global__ __launch_bounds__(256) void inter_k(float* __restrict__ out)
{
    __shared__ float qs[16][128];
    const int blk = blockIdx.x;
    const int b = blk >> 6;
    const int c = (blk >> 2) & 15;
    const int tb = blk & 3;
    const int tid = threadIdx.x;
    const int r = tid >> 1, half = tid & 1;
    const int t0 = c * LL + tb * 16;

    const float* pb = g_proj + (size_t)(b * TT + t0) * 768;
    for (int i = tid; i < 512; i += 256) {
        int tt = i >> 5, j4 = i & 31;
        *(float4*)(&qs[tt][j4 * 4]) = *(const float4*)(pb + (size_t)tt * 768 + j4 * 4);
    }
    float Creg[64];
    const float* cb = g_Cst + (size_t)(b * NC + c) * 16384 + (size_t)r * 128 + half * 64;
#pragma unroll
    for (int i = 0; i < 16; i++) {
        float4 v = *(const float4*)(cb + i * 4);
        Creg[4 * i] = v.x; Creg[4 * i + 1] = v.y;
        Creg[4 * i + 2] = v.z; Creg[4 * i + 3] = v.w;
    }
    float m0 = g_m0s[(b * NC + c) * HH + r];
    float em0a = __expf(-m0);
    __syncthreads();

    for (int tt = 0; tt < 16; tt++) {
        float acc = 0.f;
        const float* qrow = &qs[tt][half * 64];
#pragma unroll
        for (int i = 0; i < 16; i++) {
            float4 qv = *(const float4*)(qrow + i * 4);
            acc = fmaf(Creg[4 * i], qv.x, acc);
            acc = fmaf(Creg[4 * i + 1], qv.y, acc);
            acc = fmaf(Creg[4 * i + 2], qv.z, acc);
            acc = fmaf(Creg[4 * i + 3], qv.w, acc);
        }
        acc += __shfl_xor_sync(0xffffffffu, acc, 1);
        if (half == 0) {
            int t = t0 + tt;
            size_t gi = (size_t)(b * TT + t) * HH + r;
            float pm = g_PM[gi];
            float g1 = __expf(fminf(0.f, m0 - pm));
            float g2 = fminf(em0a, __expf(-pm));
            float htl = g1 * acc + g2 * g_G[gi];
            float o = g_proj[(size_t)(b * TT + t) * 768 + 640 + r];
            out[gi] = o * htl * g_rden[b * TT + t];
        }
    }
}

// ===========================================================================
extern "C" void kernel_launch(void* const* d_in, const int* in_sizes, int n_in,
                              void* d_out, int out_size)
{
    const float* x  = (const float*)d_in[0];
    const float* sW = (const float*)d_in[1];
    const float* sR = (const float*)d_in[2];
    const float* sb = (const float*)d_in[3];
    const float* Wq = (const float*)d_in[4];
    const float* Wk = (const float*)d_in[5];
    const float* Wv = (const float*)d_in[6];
    const float* Wi = (const float*)d_in[7];
    const float* Wf = (const float*)d_in[8];
    const float* Wo = (const float*)d_in[9];
    const float* bq = (const float*)d_in[10];
    const float* bk = (const float*)d_in[11];
    const float* bv = (const float*)d_in[12];
    const float* bi = (const float*)d_in[13];
    const float* bf = (const float*)d_in[14];
    const float* bo = (const float*)d_in[15];

    const int SG_SMEM = (8192 + 8448 + 8448 + 4160) * 4;   // 116,992 B
    cudaFuncSetAttribute(sg_k, cudaFuncAttributeMaxDynamicSharedMemorySize, SG_SMEM);

    // GEMM1: Wx = x @ sW^T + sb (plain layout)
    GemmArgs a1;
    for (int s = 0; s < 6; s++) {
        int ss = (s < 4) ? s : 3;
        a1.W[s] = sW + (size_t)ss * 128 * 128;
        a1.Bi[s] = sb + (size_t)ss * 128;
        a1.scale[s] = 1.f;
        a1.sigm[s] = 0;
    }
    gemm_k<<<dim3(8, 128), 256>>>(0, x, a1);

    // sLSTM scan: 4 clusters x 4 CTAs, dual-batch gate-slice
    slstm_k<<<16, 256>>>(sR);

    // GEMM2: proj = h1 @ [Wq Wk Wv Wi Wf Wo]^T + biases (k scaled, o sigmoided)
    GemmArgs a2;
    const float* Ws2[6] = {Wq, Wk, Wv, Wi, Wf, Wo};
    const float* Bs2[6] = {bq, bk, bv, bi, bf, bo};
    const float inv_sqrt_h = 0.08838834764831845f;
    for (int s = 0; s < 6; s++) {
        a2.W[s] = Ws2[s];
        a2.Bi[s] = Bs2[s];
        a2.scale[s] = (s == 1) ? inv_sqrt_h : 1.f;
        a2.sigm[s] = (s == 5) ? 1 : 0;
    }
    gemm_k<<<dim3(12, 128), 256>>>(1, nullptr, a2);

    // mLSTM chunkwise pipeline
    prep_k<<<BB * NC, 128>>>();
    sg_k<<<BB * NC, 256, SG_SMEM>>>();
    n0m0_k<<<BB, 128>>>();
    cscan_k<<<(BB * HH * HH) / 256, 256>>>();
    den_k<<<(BB * TT) / 8, 256>>>();
    inter_k<<<BB * NC * 4, 256>>>((float*)d_out);
}

// round 11
// speedup vs baseline: 2.4347x; 2.4347x over previous
#include <cuda_runtime.h>
#include <cuda_bf16.h>
#include <cstdint>

#define BB 8
#define TT 1024
#define HH 128
#define LL 64      // mLSTM chunk length
#define NC 16      // TT / LL

// ---------------- static device scratch (no allocation APIs) ---------------
__device__ float g_Wx[BB * TT * 512];     // sLSTM input projections (+sb)
__device__ float g_h1[BB * TT * HH];      // sLSTM output sequence
__device__ float g_proj[BB * TT * 768];   // mLSTM projections [q k v i f o]
__device__ float g_PM[BB * TT * HH];      // prefix-max of u within chunk
__device__ float g_Vt[BB * TT * HH];      // v * e^u
__device__ float g_P[BB * TT * HH];       // prefix-sum of k * e^u
__device__ float g_G[BB * TT * HH];       // intra-chunk numerator (pre e^{-M})
__device__ float g_Gc[BB * NC * HH * HH]; // per-chunk  Vt^T K
__device__ float g_Cst[BB * NC * HH * HH];// C state at each chunk start
__device__ float g_aL[BB * NC * HH];      // chunk-final cumsum(f)
__device__ float g_m0s[BB * NC * HH];     // m at chunk start
__device__ float g_n0s[BB * NC * HH];     // n at chunk start

static __device__ __forceinline__ unsigned su32(const void* p) {
    return (unsigned)__cvta_generic_to_shared(p);
}

// ---- f32x2 packed helpers (sm_100+) ----
static __device__ __forceinline__ unsigned long long pack2(float a, float b) {
    unsigned long long r;
    asm("mov.b64 %0, {%1, %2};" : "=l"(r) : "f"(a), "f"(b));
    return r;
}
static __device__ __forceinline__ void fma2(unsigned long long& d,
                                            unsigned long long a,
                                            unsigned long long b) {
    asm("fma.rn.f32x2 %0, %1, %2, %0;" : "+l"(d) : "l"(a), "l"(b));
}
static __device__ __forceinline__ float2 unpack2(unsigned long long v) {
    float2 f;
    asm("mov.b64 {%0, %1}, %2;" : "=f"(f.x), "=f"(f.y) : "l"(v));
    return f;
}
static __device__ __forceinline__ float tanh_fast(float x) {
    float r;
    asm("tanh.approx.f32 %0, %1;" : "=f"(r) : "f"(x));
    return r;
}

extern __shared__ float dsm[];

// ===========================================================================
// GEMM: Out[m][n] = (sum_k X[m][k]*Wseg[nloc][k] + Bseg[nloc]) * scale[seg]
// 128x64 tile, 256 threads, 8m x 4n micro-tile, m-paired FFMA2.
// ===========================================================================
struct GemmArgs {
    const float* W[6];
    const float* Bi[6];
    float scale[6];
    int sigm[6];
};

#define GEMM_SMEM ((64 * 132 + 64 * 68) * 4)

__global__ __launch_bounds__(256) void gemm_k(int mode, const float* __restrict__ Xp, GemmArgs a)
{
    const int K = 128;
    const int Ntot = (mode == 0) ? 512 : 768;
    const float* __restrict__ X = (mode == 0) ? Xp : g_h1;
    float* __restrict__ Out = (mode == 0) ? g_Wx : g_proj;

    float* Xs = dsm;               // [64][132]  k-major, m minor
    float* Ws = dsm + 64 * 132;    // [64][68]   k-major, n minor

    const int bm = blockIdx.y * 128;
    const int bn = blockIdx.x * 64;
    const int seg = bn >> 7;
    const int nl0 = bn & 127;
    const float* __restrict__ W = a.W[seg];
    const int tid = threadIdx.x;

    const int tx = tid & 15, ty = tid >> 4;   // tx: 4n, ty: 8m
    unsigned long long acc[4][4];             // [m-pair][n]
#pragma unroll
    for (int i = 0; i < 4; i++)
#pragma unroll
        for (int j = 0; j < 4; j++) acc[i][j] = 0ull;

    const int c4 = tid & 15;   // k-float4 group
    const int r0 = tid >> 4;

    for (int k0 = 0; k0 < K; k0 += 64) {
        __syncthreads();
        // X chunk: 128 m rows, store transposed [k][m]
#pragma unroll
        for (int rr = r0; rr < 128; rr += 16) {
            float4 xv = *(const float4*)&X[(size_t)(bm + rr) * K + k0 + c4 * 4];
            Xs[(c4 * 4 + 0) * 132 + rr] = xv.x;
            Xs[(c4 * 4 + 1) * 132 + rr] = xv.y;
            Xs[(c4 * 4 + 2) * 132 + rr] = xv.z;
            Xs[(c4 * 4 + 3) * 132 + rr] = xv.w;
        }
        // W chunk: 64 n rows, store transposed [k][n]
#pragma unroll
        for (int rr = r0; rr < 64; rr += 16) {
            float4 wv = *(const float4*)&W[(size_t)(nl0 + rr) * K + k0 + c4 * 4];
            Ws[(c4 * 4 + 0) * 68 + rr] = wv.x;
            Ws[(c4 * 4 + 1) * 68 + rr] = wv.y;
            Ws[(c4 * 4 + 2) * 68 + rr] = wv.z;
            Ws[(c4 * 4 + 3) * 68 + rr] = wv.w;
        }
        __syncthreads();
#pragma unroll 4
        for (int k = 0; k < 64; k++) {
            ulonglong2 xa = *(const ulonglong2*)&Xs[k * 132 + ty * 8];      // m 0..3
            ulonglong2 xb = *(const ulonglong2*)&Xs[k * 132 + ty * 8 + 4];  // m 4..7
            float4 wv = *(const float4*)&Ws[k * 68 + tx * 4];
            unsigned long long w0 = pack2(wv.x, wv.x);
            unsigned long long w1 = pack2(wv.y, wv.y);
            unsigned long long w2 = pack2(wv.z, wv.z);
            unsigned long long w3 = pack2(wv.w, wv.w);
            fma2(acc[0][0], xa.x, w0); fma2(acc[0][1], xa.x, w1);
            fma2(acc[0][2], xa.x, w2); fma2(acc[0][3], xa.x, w3);
            fma2(acc[1][0], xa.y, w0); fma2(acc[1][1], xa.y, w1);
            fma2(acc[1][2], xa.y, w2); fma2(acc[1][3], xa.y, w3);
            fma2(acc[2][0], xb.x, w0); fma2(acc[2][1], xb.x, w1);
            fma2(acc[2][2], xb.x, w2); fma2(acc[2][3], xb.x, w3);
            fma2(acc[3][0], xb.y, w0); fma2(acc[3][1], xb.y, w1);
            fma2(acc[3][2], xb.y, w2); fma2(acc[3][3], xb.y, w3);
        }
    }

    const float sc = a.scale[seg];
    const int sg = a.sigm[seg];
    const float* __restrict__ Bp = a.Bi[seg];
#pragma unroll
    for (int i = 0; i < 8; i++) {
        int m = bm + ty * 8 + i;
        int mp = i >> 1, hs = i & 1;
#pragma unroll
        for (int j = 0; j < 4; j++) {
            float2 p = unpack2(acc[mp][j]);
            float v = ((hs ? p.y : p.x) + Bp[nl0 + tx * 4 + j]) * sc;
            if (sg) v = 1.f / (1.f + __expf(-v));
            Out[(size_t)m * Ntot + bn + tx * 4 + j] = v;
        }
    }
}

// ===========================================================================
// sLSTM scan (R5 design, verbatim): cluster of 4 CTAs per batch, 128 thr/CTA.
// thread = (unit_local, gate); gates of a unit sit in 4 adjacent lanes.
// matvec in packed f32x2; h exchange via DSMEM + per-CTA mbarrier.
// ===========================================================================
__global__ void __cluster_dims__(4, 1, 1) __launch_bounds__(128, 1)
slstm_k(const float* __restrict__ sR)
{
    __shared__ __align__(16) float h_s[2][HH];
    __shared__ __align__(8) unsigned long long mbar;

    const int tid = threadIdx.x;
    const unsigned rank = (unsigned)(blockIdx.x & 3);
    const int batch = blockIdx.x >> 2;
    const int gate = tid & 3;
    const int ul = tid >> 2;
    const int gu = (int)rank * 32 + ul;
    const int row = gate * 128 + gu;

    unsigned long long w2[64];
    {
        const float4* wr = (const float4*)(sR + (size_t)row * 128);
#pragma unroll
        for (int k4 = 0; k4 < 32; k4++) {
            float4 v = wr[k4];
            w2[2 * k4 + 0] = pack2(v.x, v.y);
            w2[2 * k4 + 1] = pack2(v.z, v.w);
        }
    }
    h_s[0][tid] = 0.f;
    h_s[1][tid] = 0.f;
    if (tid == 0) {
        unsigned a = su32(&mbar);
        asm volatile("mbarrier.init.shared.b64 [%0], %1;" :: "r"(a), "r"(128) : "memory");
    }
    __syncthreads();
    asm volatile("barrier.cluster.arrive;\n\tbarrier.cluster.wait;\n" ::: "memory");

    const unsigned dst = (rank + (unsigned)gate) & 3;
    const unsigned mbar_l = su32(&mbar);
    unsigned mbar_d, h_d0;
    {
        unsigned hl0 = su32(&h_s[0][gu]);
        asm("mapa.shared::cluster.u32 %0, %1, %2;" : "=r"(mbar_d) : "r"(mbar_l), "r"(dst));
        asm("mapa.shared::cluster.u32 %0, %1, %2;" : "=r"(h_d0) : "r"(hl0), "r"(dst));
    }

    float c = 0.f, n = 0.f, m = 0.f;
    const float* __restrict__ wx = g_Wx + (size_t)batch * TT * 512 + row;
    float* __restrict__ h1o = g_h1 + (size_t)batch * TT * HH;

    const int lw = tid & 31;
    const int gb = lw & ~3;

    float wx_cur = wx[0];

    for (int t = 0; t < TT; t++) {
        const int buf = t & 1;
        float wx_nxt = (t + 1 < TT) ? wx[(size_t)(t + 1) * 512] : 0.f;

        unsigned long long a0 = 0ull, a1 = 0ull, a2 = 0ull, a3 = 0ull;
        const ulonglong2* h2 = (const ulonglong2*)h_s[buf];
#pragma unroll
        for (int k = 0; k < 16; k++) {
            ulonglong2 hA = h2[2 * k];
            ulonglong2 hB = h2[2 * k + 1];
            fma2(a0, w2[4 * k + 0], hA.x);
            fma2(a1, w2[4 * k + 1], hA.y);
            fma2(a2, w2[4 * k + 2], hB.x);
            fma2(a3, w2[4 * k + 3], hB.y);
        }
        float2 f0 = unpack2(a0), f1 = unpack2(a1), f2 = unpack2(a2), f3 = unpack2(a3);
        float g = (((f0.x + f0.y) + (f1.x + f1.y)) + ((f2.x + f2.y) + (f3.x + f3.y))) + wx_cur;

        __syncthreads();

        float gi = __shfl_sync(0xffffffffu, g, gb + 0, 32);
        float gf = __shfl_sync(0xffffffffu, g, gb + 1, 32);
        float gz = __shfl_sync(0xffffffffu, g, gb + 2, 32);
        float go = __shfl_sync(0xffffffffu, g, gb + 3, 32);

        float mn = fmaxf(gf + m, gi);
        float ii = __expf(gi - mn);
        float ff = __expf(gf + m - mn);
        c = ff * c + ii * tanh_fast(gz);
        n = ff * n + ii;
        m = mn;
        float sg = __fdividef(1.f, 1.f + __expf(-go));
        float hn = __fdividef(c, n) * sg;

        const int nb = buf ^ 1;
        unsigned haddr = h_d0 + (unsigned)(nb * (HH * 4));
        asm volatile("st.shared::cluster.f32 [%0], %1;" :: "r"(haddr), "f"(hn) : "memory");
        if (gate == 0) h1o[(size_t)t * HH + gu] = hn;

        asm volatile("mbarrier.arrive.release.cluster.shared::cluster.b64 _, [%0];"
                     :: "r"(mbar_d) : "memory");

        {
            unsigned par = (unsigned)(t & 1);
            asm volatile(
                "{\n\t"
                ".reg .pred P;\n\t"
                "WLOOP%=:\n\t"
                "mbarrier.try_wait.parity.acquire.cluster.shared::cta.b64 P, [%0], %1, 0x989680;\n\t"
                "@P bra.uni WDONE%=;\n\t"
                "bra.uni WLOOP%=;\n\t"
                "WDONE%=:\n\t"
                "}"
                :: "r"(mbar_l), "r"(par) : "memory");
        }
        wx_cur = wx_nxt;
    }

    asm volatile("barrier.cluster.arrive;\n\tbarrier.cluster.wait;\n" ::: "memory");
}

// ===========================================================================
// mLSTM chunkwise-parallel pipeline (R5 versions)
// ===========================================================================

__global__ __launch_bounds__(128) void prep_k()
{
    const int b = blockIdx.x >> 4;
    const int c = blockIdx.x & 15;
    const int j = threadIdx.x;
    const float* __restrict__ base = g_proj + ((size_t)(b * TT + c * LL) * 768) + j;
    float a = 0.f, pm = -1e30f, p = 0.f;
    size_t oidx = (size_t)(b * TT + c * LL) * HH + j;

    float fb[2][4], ib[2][4], vb[2][4], kb[2][4];
#pragma unroll
    for (int s = 0; s < 4; s++) {
        const float* row = base + (size_t)s * 768;
        fb[0][s] = row[512]; ib[0][s] = row[384];
        vb[0][s] = row[256]; kb[0][s] = row[128];
    }
    for (int gidx = 0; gidx < 16; gidx++) {
        const int cb = gidx & 1;
        if (gidx + 1 < 16) {
            const float* gbase = base + (size_t)(gidx + 1) * 4 * 768;
#pragma unroll
            for (int s = 0; s < 4; s++) {
                const float* row = gbase + (size_t)s * 768;
                fb[cb ^ 1][s] = row[512]; ib[cb ^ 1][s] = row[384];
                vb[cb ^ 1][s] = row[256]; kb[cb ^ 1][s] = row[128];
            }
        }
#pragma unroll
        for (int s = 0; s < 4; s++) {
            a += fb[cb][s];
            float u = ib[cb][s] - a;
            pm = fmaxf(pm, u);
            float eu = __expf(u);
            g_PM[oidx] = pm;
            g_Vt[oidx] = vb[cb][s] * eu;
            p = fmaf(kb[cb][s], eu, p);
            g_P[oidx] = p;
            oidx += HH;
        }
    }
    g_aL[(b * NC + c) * HH + j] = a;
}

__global__ __launch_bounds__(128) void n0m0_k()
{
    const int b = blockIdx.x;
    const int j = threadIdx.x;
    float m0 = 0.f, n0 = 0.f;
    for (int c = 0; c < NC; c++) {
        int ci = (b * NC + c) * HH + j;
        g_m0s[ci] = m0;
        g_n0s[ci] = n0;
        size_t li = (size_t)(b * TT + c * LL + (LL - 1)) * HH + j;
        float pml = g_PM[li];
        float pl  = g_P[li];
        float ML = fmaxf(m0, pml);
        n0 = __expf(m0 - ML) * n0 + __expf(-ML) * pl;
        m0 = g_aL[ci] + ML;
    }
}

__global__ __launch_bounds__(256) void gc_k()
{
    float* Vs = dsm;
    float* Ks = dsm + 64 * 128;
    const int b = blockIdx.x >> 4, c = blockIdx.x & 15;
    const int tid = threadIdx.x;
    const float* __restrict__ vb = g_Vt + (size_t)(b * TT + c * LL) * HH;
    const float* __restrict__ pb = g_proj + (size_t)(b * TT + c * LL) * 768;
    for (int i = tid; i < 2048; i += 256) {
        int s = i >> 5, j4 = i & 31;
        ((float4*)Vs)[i] = ((const float4*)vb)[i];
        float4 kv = *(const float4*)(pb + (size_t)s * 768 + 128 + j4 * 4);
        *(float4*)(Ks + s * 132 + j4 * 4) = kv;
    }
    __syncthreads();
    const int r0 = (tid >> 4) * 8, j0 = (tid & 15) * 8;
    float acc[8][8];
#pragma unroll
    for (int i = 0; i < 8; i++)
#pragma unroll
        for (int jj = 0; jj < 8; jj++) acc[i][jj] = 0.f;
    for (int s = 0; s < 64; s++) {
        float4 va = *(float4*)(Vs + s * 128 + r0);
        float4 vb4 = *(float4*)(Vs + s * 128 + r0 + 4);
        float4 ka = *(float4*)(Ks + s * 132 + j0);
        float4 kb = *(float4*)(Ks + s * 132 + j0 + 4);
        float vr[8] = {va.x, va.y, va.z, va.w, vb4.x, vb4.y, vb4.z, vb4.w};
        float kj[8] = {ka.x, ka.y, ka.z, ka.w, kb.x, kb.y, kb.z, kb.w};
#pragma unroll
        for (int i = 0; i < 8; i++)
#pragma unroll
            for (int jj = 0; jj < 8; jj++)
                acc[i][jj] = fmaf(vr[i], kj[jj], acc[i][jj]);
    }
    float* gout = g_Gc + (size_t)(b * NC + c) * (HH * HH);
#pragma unroll
    for (int i = 0; i < 8; i++)
#pragma unroll
        for (int jj = 0; jj < 8; jj += 4) {
            float4 v = {acc[i][jj], acc[i][jj + 1], acc[i][jj + 2], acc[i][jj + 3]};
            *(float4*)(gout + (size_t)(r0 + i) * HH + j0 + jj) = v;
        }
}

__global__ __launch_bounds__(256) void sg_k()
{
    float* Qs = dsm;
    float* KV = dsm + 64 * 128;
    float* Ss = dsm + 64 * 128 + 64 * 132;
    const int b = blockIdx.x >> 4, c = blockIdx.x & 15;
    const int tid = threadIdx.x;
    const float* __restrict__ pb = g_proj + (size_t)(b * TT + c * LL) * 768;
    const float* __restrict__ vb = g_Vt + (size_t)(b * TT + c * LL) * HH;
    for (int i = tid; i < 2048; i += 256) {
        int s = i >> 5, j4 = i & 31;
        *(float4*)(Qs + s * 128 + j4 * 4) = *(const float4*)(pb + (size_t)s * 768 + j4 * 4);
        *(float4*)(KV + s * 132 + j4 * 4) = *(const float4*)(pb + (size_t)s * 768 + 128 + j4 * 4);
    }
    __syncthreads();
    {
        const int t0 = (tid >> 4) * 4, s0 = (tid & 15) * 4;
        float acc[4][4];
#pragma unroll
        for (int i = 0; i < 4; i++)
#pragma unroll
            for (int s = 0; s < 4; s++) acc[i][s] = 0.f;
        for (int jj = 0; jj < 128; jj += 4) {
            float4 q[4], k[4];
#pragma unroll
            for (int i = 0; i < 4; i++) q[i] = *(float4*)(Qs + (t0 + i) * 128 + jj);
#pragma unroll
            for (int s = 0; s < 4; s++) k[s] = *(float4*)(KV + (s0 + s) * 132 + jj);
#pragma unroll
            for (int i = 0; i < 4; i++)
#pragma unroll
                for (int s = 0; s < 4; s++)
                    acc[i][s] += q[i].x * k[s].x + q[i].y * k[s].y
                               + q[i].z * k[s].z + q[i].w * k[s].w;
        }
#pragma unroll
        for (int i = 0; i < 4; i++)
#pragma unroll
            for (int s = 0; s < 4; s++)
                Ss[(t0 + i) * 65 + s0 + s] = (s0 + s <= t0 + i) ? acc[i][s] : 0.f;
    }
    __syncthreads();
    for (int i = tid; i < 2048; i += 256) {
        int s = i >> 5, j4 = i & 31;
        *(float4*)(KV + s * 132 + j4 * 4) = *(const float4*)(vb + (size_t)s * HH + j4 * 4);
    }
    __syncthreads();
    {
        const int t0 = (tid >> 5) * 8, r0 = (tid & 31) * 4;
        float acc[8][4];
#pragma unroll
        for (int i = 0; i < 8; i++)
#pragma unroll
            for (int jj = 0; jj < 4; jj++) acc[i][jj] = 0.f;
        for (int s = 0; s < 64; s++) {
            float4 v = *(float4*)(KV + s * 132 + r0);
#pragma unroll
            for (int i = 0; i < 8; i++) {
                float sv = Ss[(t0 + i) * 65 + s];
                acc[i][0] = fmaf(sv, v.x, acc[i][0]);
                acc[i][1] = fmaf(sv, v.y, acc[i][1]);
                acc[i][2] = fmaf(sv, v.z, acc[i][2]);
                acc[i][3] = fmaf(sv, v.w, acc[i][3]);
            }
        }
        float* gout = g_G + (size_t)(b * TT + c * LL) * HH;
#pragma unroll
        for (int i = 0; i < 8; i++) {
            float4 o4 = {acc[i][0], acc[i][1], acc[i][2], acc[i][3]};
            *(float4*)(gout + (size_t)(t0 + i) * HH + r0) = o4;
        }
    }
}

__global__ __launch_bounds__(256) void cscan_k()
{
    int idx = blockIdx.x * 256 + threadIdx.x;
    int b = idx >> 14;
    int rj = idx & 16383;
    int r = rj >> 7;
    float C = 0.f;
    for (int c = 0; c < NC; c++) {
        size_t so = (size_t)(b * NC + c) * 16384 + rj;
        g_Cst[so] = C;
        float m0 = g_m0s[(b * NC + c) * HH + r];
        float pml = g_PM[(size_t)(b * TT + c * LL + LL - 1) * HH + r];
        float ML = fmaxf(m0, pml);
        C = __expf(m0 - ML) * C + __expf(-ML) * g_Gc[so];
    }
}

// ---- final: h = o * (e^{m0-M} C0 q + e^{-M} G) / den    (den fused in)
__global__ __launch_bounds__(256) void inter_k(float* __restrict__ out)
{
    __shared__ float qs[16][128];
    __shared__ float rden_s[16];
    const int blk = blockIdx.x;
    const int b = blk >> 6;
    const int c = (blk >> 2) & 15;
    const int tb = blk & 3;
    const int tid = threadIdx.x;
    const int r = tid >> 1, half = tid & 1;
    const int t0 = c * LL + tb * 16;

    const float* pb = g_proj + (size_t)(b * TT + t0) * 768;
    for (int i = tid; i < 512; i += 256) {
        int tt = i >> 5, j4 = i & 31;
        *(float4*)(&qs[tt][j4 * 4]) = *(const float4*)(pb + (size_t)tt * 768 + j4 * 4);
    }
    float Creg[64];
    const float* cb = g_Cst + (size_t)(b * NC + c) * 16384 + (size_t)r * 128 + half * 64;
#pragma unroll
    for (int i = 0; i < 16; i++) {
        float4 v = *(const float4*)(cb + i * 4);
        Creg[4 * i] = v.x; Creg[4 * i + 1] = v.y;
        Creg[4 * i + 2] = v.z; Creg[4 * i + 3] = v.w;
    }
    float m0 = g_m0s[(b * NC + c) * HH + r];
    float em0a = __expf(-m0);
    __syncthreads();   // qs ready

    // ---- fused denominators for the 16 timesteps of this block ----
    {
        const int tt = tid >> 4, jg = tid & 15, j0 = jg * 8;
        const int ci = (b * NC + c) * HH;
        const size_t gi2 = (size_t)(b * TT + t0 + tt) * HH;
        float d = 0.f;
#pragma unroll
        for (int s = 0; s < 8; s++) {
            int j = j0 + s;
            float m0j = g_m0s[ci + j];
            float pmj = g_PM[gi2 + j];
            float g1 = __expf(fminf(0.f, m0j - pmj));
            float g2 = fminf(__expf(-m0j), __expf(-pmj));
            float nv = g1 * g_n0s[ci + j] + g2 * g_P[gi2 + j];
            d = fmaf(qs[tt][j], nv, d);
        }
        d += __shfl_xor_sync(0xffffffffu, d, 1);
        d += __shfl_xor_sync(0xffffffffu, d, 2);
        d += __shfl_xor_sync(0xffffffffu, d, 4);
        d += __shfl_xor_sync(0xffffffffu, d, 8);
        if (jg == 0) rden_s[tt] = 1.f / fmaxf(fabsf(d), 1.f);
    }
    __syncthreads();

    for (int tt = 0; tt < 16; tt++) {
        float acc = 0.f;
        const float* qrow = &qs[tt][half * 64];
#pragma unroll
        for (int i = 0; i < 16; i++) {
            float4 qv = *(const float4*)(qrow + i * 4);
            acc = fmaf(Creg[4 * i], qv.x, acc);
            acc = fmaf(Creg[4 * i + 1], qv.y, acc);
            acc = fmaf(Creg[4 * i + 2], qv.z, acc);
            acc = fmaf(Creg[4 * i + 3], qv.w, acc);
        }
        acc += __shfl_xor_sync(0xffffffffu, acc, 1);
        if (half == 0) {
            int t = t0 + tt;
            size_t gi = (size_t)(b * TT + t) * HH + r;
            float pm = g_PM[gi];
            float g1 = __expf(fminf(0.f, m0 - pm));
            float g2 = fminf(em0a, __expf(-pm));
            float htl = g1 * acc + g2 * g_G[gi];
            float o = g_proj[(size_t)(b * TT + t) * 768 + 640 + r];
            out[gi] = o * htl * rden_s[tt];
        }
    }
}

// ===========================================================================
extern "C" void kernel_launch(void* const* d_in, const int* in_sizes, int n_in,
                              void* d_out, int out_size)
{
    const float* x  = (const float*)d_in[0];
    const float* sW = (const float*)d_in[1];
    const float* sR = (const float*)d_in[2];
    const float* sb = (const float*)d_in[3];
    const float* Wq = (const float*)d_in[4];
    const float* Wk = (const float*)d_in[5];
    const float* Wv = (const float*)d_in[6];
    const float* Wi = (const float*)d_in[7];
    const float* Wf = (const float*)d_in[8];
    const float* Wo = (const float*)d_in[9];
    const float* bq = (const float*)d_in[10];
    const float* bk = (const float*)d_in[11];
    const float* bv = (const float*)d_in[12];
    const float* bi = (const float*)d_in[13];
    const float* bf = (const float*)d_in[14];
    const float* bo = (const float*)d_in[15];

    const int GC_SMEM = (64 * 128 + 64 * 132) * 4;
    const int SG_SMEM = (64 * 128 + 64 * 132 + 64 * 65) * 4;
    cudaFuncSetAttribute(gc_k, cudaFuncAttributeMaxDynamicSharedMemorySize, GC_SMEM);
    cudaFuncSetAttribute(sg_k, cudaFuncAttributeMaxDynamicSharedMemorySize, SG_SMEM);
    cudaFuncSetAttribute(gemm_k, cudaFuncAttributeMaxDynamicSharedMemorySize, GEMM_SMEM);

    // GEMM1: Wx = x @ sW^T + sb
    GemmArgs a1;
    for (int s = 0; s < 6; s++) {
        int ss = (s < 4) ? s : 3;
        a1.W[s] = sW + (size_t)ss * 128 * 128;
        a1.Bi[s] = sb + (size_t)ss * 128;
        a1.scale[s] = 1.f;
        a1.sigm[s] = 0;
    }
    gemm_k<<<dim3(8, 64), 256, GEMM_SMEM>>>(0, x, a1);

    // sLSTM scan (cluster 4 per batch)
    slstm_k<<<32, 128>>>(sR);

    // GEMM2: proj = h1 @ [Wq Wk Wv Wi Wf Wo]^T + biases (k scaled, o sigmoided)
    GemmArgs a2;
    const float* Ws2[6] = {Wq, Wk, Wv, Wi, Wf, Wo};
    const float* Bs2[6] = {bq, bk, bv, bi, bf, bo};
    const float inv_sqrt_h = 0.08838834764831845f;
    for (int s = 0; s < 6; s++) {
        a2.W[s] = Ws2[s];
        a2.Bi[s] = Bs2[s];
        a2.scale[s] = (s == 1) ? inv_sqrt_h : 1.f;
        a2.sigm[s] = (s == 5) ? 1 : 0;
    }
    gemm_k<<<dim3(12, 64), 256, GEMM_SMEM>>>(1, nullptr, a2);

    // mLSTM chunkwise pipeline
    prep_k<<<BB * NC, 128>>>();
    gc_k<<<BB * NC, 256, GC_SMEM>>>();
    sg_k<<<BB * NC, 256, SG_SMEM>>>();
    n0m0_k<<<BB, 128>>>();
    cscan_k<<<(BB * HH * HH) / 256, 256>>>();
    inter_k<<<BB * NC * 4, 256>>>((float*)d_out);
}

// round 12
// speedup vs baseline: 2.5710x; 1.0560x over previous
#include <cuda_runtime.h>
#include <cuda_bf16.h>
#include <cstdint>

#define BB 8
#define TT 1024
#define HH 128
#define LL 64      // mLSTM chunk length
#define NC 16      // TT / LL

// ---------------- static device scratch (no allocation APIs) ---------------
__device__ float g_Wx[BB * TT * 512];     // sLSTM input projections (+sb)
__device__ float g_h1[BB * TT * HH];      // sLSTM output sequence
__device__ float g_proj[BB * TT * 768];   // mLSTM projections [q k v i f o]
__device__ float g_PM[BB * TT * HH];      // prefix-max of u within chunk
__device__ float g_Vt[BB * TT * HH];      // v * e^u
__device__ float g_P[BB * TT * HH];       // prefix-sum of k * e^u
__device__ float g_G[BB * TT * HH];       // intra-chunk numerator (pre e^{-M})
__device__ float g_Gc[BB * NC * HH * HH]; // per-chunk  Vt^T K
__device__ float g_Cst[BB * NC * HH * HH];// C state at each chunk start
__device__ float g_aL[BB * NC * HH];      // chunk-final cumsum(f)
__device__ float g_m0s[BB * NC * HH];     // m at chunk start
__device__ float g_n0s[BB * NC * HH];     // n at chunk start

static __device__ __forceinline__ unsigned su32(const void* p) {
    return (unsigned)__cvta_generic_to_shared(p);
}

// ---- f32x2 packed helpers (sm_100+) ----
static __device__ __forceinline__ unsigned long long pack2(float a, float b) {
    unsigned long long r;
    asm("mov.b64 %0, {%1, %2};" : "=l"(r) : "f"(a), "f"(b));
    return r;
}
static __device__ __forceinline__ void fma2(unsigned long long& d,
                                            unsigned long long a,
                                            unsigned long long b) {
    asm("fma.rn.f32x2 %0, %1, %2, %0;" : "+l"(d) : "l"(a), "l"(b));
}
static __device__ __forceinline__ float2 unpack2(unsigned long long v) {
    float2 f;
    asm("mov.b64 {%0, %1}, %2;" : "=f"(f.x), "=f"(f.y) : "l"(v));
    return f;
}
static __device__ __forceinline__ float tanh_fast(float x) {
    float r;
    asm("tanh.approx.f32 %0, %1;" : "=f"(r) : "f"(x));
    return r;
}

extern __shared__ float dsm[];

// ===========================================================================
// GEMM: Out[m][n] = (sum_k X[m][k]*Wseg[nloc][k] + Bseg[nloc]) * scale[seg]
// 128x64 tile, 256 threads, 8m x 4n micro-tile, m-paired FFMA2. (R11)
// ===========================================================================
struct GemmArgs {
    const float* W[6];
    const float* Bi[6];
    float scale[6];
    int sigm[6];
};

#define GEMM_SMEM ((64 * 132 + 64 * 68) * 4)

__global__ __launch_bounds__(256) void gemm_k(int mode, const float* __restrict__ Xp, GemmArgs a)
{
    const int K = 128;
    const int Ntot = (mode == 0) ? 512 : 768;
    const float* __restrict__ X = (mode == 0) ? Xp : g_h1;
    float* __restrict__ Out = (mode == 0) ? g_Wx : g_proj;

    float* Xs = dsm;               // [64][132]
    float* Ws = dsm + 64 * 132;    // [64][68]

    const int bm = blockIdx.y * 128;
    const int bn = blockIdx.x * 64;
    const int seg = bn >> 7;
    const int nl0 = bn & 127;
    const float* __restrict__ W = a.W[seg];
    const int tid = threadIdx.x;

    const int tx = tid & 15, ty = tid >> 4;
    unsigned long long acc[4][4];
#pragma unroll
    for (int i = 0; i < 4; i++)
#pragma unroll
        for (int j = 0; j < 4; j++) acc[i][j] = 0ull;

    const int c4 = tid & 15;
    const int r0 = tid >> 4;

    for (int k0 = 0; k0 < K; k0 += 64) {
        __syncthreads();
#pragma unroll
        for (int rr = r0; rr < 128; rr += 16) {
            float4 xv = *(const float4*)&X[(size_t)(bm + rr) * K + k0 + c4 * 4];
            Xs[(c4 * 4 + 0) * 132 + rr] = xv.x;
            Xs[(c4 * 4 + 1) * 132 + rr] = xv.y;
            Xs[(c4 * 4 + 2) * 132 + rr] = xv.z;
            Xs[(c4 * 4 + 3) * 132 + rr] = xv.w;
        }
#pragma unroll
        for (int rr = r0; rr < 64; rr += 16) {
            float4 wv = *(const float4*)&W[(size_t)(nl0 + rr) * K + k0 + c4 * 4];
            Ws[(c4 * 4 + 0) * 68 + rr] = wv.x;
            Ws[(c4 * 4 + 1) * 68 + rr] = wv.y;
            Ws[(c4 * 4 + 2) * 68 + rr] = wv.z;
            Ws[(c4 * 4 + 3) * 68 + rr] = wv.w;
        }
        __syncthreads();
#pragma unroll 4
        for (int k = 0; k < 64; k++) {
            ulonglong2 xa = *(const ulonglong2*)&Xs[k * 132 + ty * 8];
            ulonglong2 xb = *(const ulonglong2*)&Xs[k * 132 + ty * 8 + 4];
            float4 wv = *(const float4*)&Ws[k * 68 + tx * 4];
            unsigned long long w0 = pack2(wv.x, wv.x);
            unsigned long long w1 = pack2(wv.y, wv.y);
            unsigned long long w2 = pack2(wv.z, wv.z);
            unsigned long long w3 = pack2(wv.w, wv.w);
            fma2(acc[0][0], xa.x, w0); fma2(acc[0][1], xa.x, w1);
            fma2(acc[0][2], xa.x, w2); fma2(acc[0][3], xa.x, w3);
            fma2(acc[1][0], xa.y, w0); fma2(acc[1][1], xa.y, w1);
            fma2(acc[1][2], xa.y, w2); fma2(acc[1][3], xa.y, w3);
            fma2(acc[2][0], xb.x, w0); fma2(acc[2][1], xb.x, w1);
            fma2(acc[2][2], xb.x, w2); fma2(acc[2][3], xb.x, w3);
            fma2(acc[3][0], xb.y, w0); fma2(acc[3][1], xb.y, w1);
            fma2(acc[3][2], xb.y, w2); fma2(acc[3][3], xb.y, w3);
        }
    }

    const float sc = a.scale[seg];
    const int sg = a.sigm[seg];
    const float* __restrict__ Bp = a.Bi[seg];
#pragma unroll
    for (int i = 0; i < 8; i++) {
        int m = bm + ty * 8 + i;
        int mp = i >> 1, hs = i & 1;
#pragma unroll
        for (int j = 0; j < 4; j++) {
            float2 p = unpack2(acc[mp][j]);
            float v = ((hs ? p.y : p.x) + Bp[nl0 + tx * 4 + j]) * sc;
            if (sg) v = 1.f / (1.f + __expf(-v));
            Out[(size_t)m * Ntot + bn + tx * 4 + j] = v;
        }
    }
}

// ===========================================================================
// sLSTM scan: cluster of 4 CTAs per batch (R5 mapping), h exchange via
// st.async + mbarrier complete_tx (single fused data+signal message).
// Two ping-pong barriers; stores at step t target mbar[(t+1)&1].
// ===========================================================================
__global__ void __cluster_dims__(4, 1, 1) __launch_bounds__(128, 1)
slstm_k(const float* __restrict__ sR)
{
    __shared__ __align__(16) float h_s[2][HH];
    __shared__ __align__(8) unsigned long long mb[2];

    const int tid = threadIdx.x;
    const unsigned rank = (unsigned)(blockIdx.x & 3);
    const int batch = blockIdx.x >> 2;
    const int gate = tid & 3;
    const int ul = tid >> 2;
    const int gu = (int)rank * 32 + ul;
    const int row = gate * 128 + gu;

    unsigned long long w2[64];
    {
        const float4* wr = (const float4*)(sR + (size_t)row * 128);
#pragma unroll
        for (int k4 = 0; k4 < 32; k4++) {
            float4 v = wr[k4];
            w2[2 * k4 + 0] = pack2(v.x, v.y);
            w2[2 * k4 + 1] = pack2(v.z, v.w);
        }
    }
    h_s[0][tid] = 0.f;
    h_s[1][tid] = 0.f;
    const unsigned mb0_l = su32(&mb[0]);
    const unsigned mb1_l = su32(&mb[1]);
    if (tid == 0) {
        asm volatile("mbarrier.init.shared.b64 [%0], %1;" :: "r"(mb0_l), "r"(1) : "memory");
        asm volatile("mbarrier.init.shared.b64 [%0], %1;" :: "r"(mb1_l), "r"(1) : "memory");
        // prologue expect for B_1 (= mb[1], receives step-0 stores: 128 x 4B)
        asm volatile("mbarrier.arrive.expect_tx.release.cluster.shared::cta.b64 _, [%0], %1;"
                     :: "r"(mb1_l), "r"(512) : "memory");
    }
    __syncthreads();
    asm volatile("barrier.cluster.arrive;\n\tbarrier.cluster.wait;\n" ::: "memory");

    // destination CTA of this thread's h message
    const unsigned dst = (rank + (unsigned)gate) & 3;
    unsigned mbd[2], h_d0;
    {
        unsigned hl0 = su32(&h_s[0][gu]);
        asm("mapa.shared::cluster.u32 %0, %1, %2;" : "=r"(mbd[0]) : "r"(mb0_l), "r"(dst));
        asm("mapa.shared::cluster.u32 %0, %1, %2;" : "=r"(mbd[1]) : "r"(mb1_l), "r"(dst));
        asm("mapa.shared::cluster.u32 %0, %1, %2;" : "=r"(h_d0) : "r"(hl0), "r"(dst));
    }

    float c = 0.f, n = 0.f, m = 0.f;
    const float* __restrict__ wx = g_Wx + (size_t)batch * TT * 512 + row;
    float* __restrict__ h1o = g_h1 + (size_t)batch * TT * HH;

    const int lw = tid & 31;
    const int gb = lw & ~3;

    int ph0 = 0, ph1 = 0;      // next wait parity for mb[0] / mb[1]
    float wx_cur = wx[0];

    for (int t = 0; t < TT; t++) {
        const int buf = t & 1;

        // expect_tx for B_{t+2} (= mb[t&1]) — ordered before this CTA's step-t
        // stores, hence (via the B_{t+1} chain) before any tx targeting B_{t+2}.
        if (tid == 0) {
            asm volatile("mbarrier.arrive.expect_tx.release.cluster.shared::cta.b64 _, [%0], %1;"
                         :: "r"(buf ? mb1_l : mb0_l), "r"(512) : "memory");
        }

        float wx_nxt = (t + 1 < TT) ? wx[(size_t)(t + 1) * 512] : 0.f;

        unsigned long long a0 = 0ull, a1 = 0ull, a2 = 0ull, a3 = 0ull;
        const ulonglong2* h2 = (const ulonglong2*)h_s[buf];
#pragma unroll
        for (int k = 0; k < 16; k++) {
            ulonglong2 hA = h2[2 * k];
            ulonglong2 hB = h2[2 * k + 1];
            fma2(a0, w2[4 * k + 0], hA.x);
            fma2(a1, w2[4 * k + 1], hA.y);
            fma2(a2, w2[4 * k + 2], hB.x);
            fma2(a3, w2[4 * k + 3], hB.y);
        }
        float2 f0 = unpack2(a0), f1 = unpack2(a1), f2 = unpack2(a2), f3 = unpack2(a3);
        float g = (((f0.x + f0.y) + (f1.x + f1.y)) + ((f2.x + f2.y) + (f3.x + f3.y))) + wx_cur;

        __syncthreads();   // all local lanes done reading h_s[buf]

        float gi = __shfl_sync(0xffffffffu, g, gb + 0, 32);
        float gf = __shfl_sync(0xffffffffu, g, gb + 1, 32);
        float gz = __shfl_sync(0xffffffffu, g, gb + 2, 32);
        float go = __shfl_sync(0xffffffffu, g, gb + 3, 32);

        float mn = fmaxf(gf + m, gi);
        float ii = __expf(gi - mn);
        float ff = __expf(gf + m - mn);
        c = ff * c + ii * tanh_fast(gz);
        n = ff * n + ii;
        m = mn;
        float sg = __fdividef(1.f, 1.f + __expf(-go));
        float hn = __fdividef(c, n) * sg;

        // fused data+tx message: h for step t+1 -> dst's h_s[(t+1)&1], mb[(t+1)&1]
        const int nb = buf ^ 1;
        unsigned haddr = h_d0 + (unsigned)(nb * (HH * 4));
        asm volatile("st.async.shared::cluster.mbarrier::complete_tx::bytes.b32 [%0], %1, [%2];"
                     :: "r"(haddr), "r"(__float_as_uint(hn)), "r"(mbd[nb]) : "memory");
        if (gate == 0) h1o[(size_t)t * HH + gu] = hn;

        // wait B_{t+1} = mb[(t+1)&1]
        if (nb) {
            asm volatile(
                "{\n\t.reg .pred P;\n\t"
                "W1%=:\n\t"
                "mbarrier.try_wait.parity.acquire.cluster.shared::cta.b64 P, [%0], %1, 0x989680;\n\t"
                "@P bra.uni D1%=;\n\tbra.uni W1%=;\n\tD1%=:\n\t}"
                :: "r"(mb1_l), "r"(ph1) : "memory");
            ph1 ^= 1;
        } else {
            asm volatile(
                "{\n\t.reg .pred P;\n\t"
                "W0%=:\n\t"
                "mbarrier.try_wait.parity.acquire.cluster.shared::cta.b64 P, [%0], %1, 0x989680;\n\t"
                "@P bra.uni D0%=;\n\tbra.uni W0%=;\n\tD0%=:\n\t}"
                :: "r"(mb0_l), "r"(ph0) : "memory");
            ph0 ^= 1;
        }
        wx_cur = wx_nxt;
    }

    asm volatile("barrier.cluster.arrive;\n\tbarrier.cluster.wait;\n" ::: "memory");
}

// ===========================================================================
// mLSTM chunkwise-parallel pipeline (R11 versions, unchanged)
// ===========================================================================

__global__ __launch_bounds__(128) void prep_k()
{
    const int b = blockIdx.x >> 4;
    const int c = blockIdx.x & 15;
    const int j = threadIdx.x;
    const float* __restrict__ base = g_proj + ((size_t)(b * TT + c * LL) * 768) + j;
    float a = 0.f, pm = -1e30f, p = 0.f;
    size_t oidx = (size_t)(b * TT + c * LL) * HH + j;

    float fb[2][4], ib[2][4], vb[2][4], kb[2][4];
#pragma unroll
    for (int s = 0; s < 4; s++) {
        const float* row = base + (size_t)s * 768;
        fb[0][s] = row[512]; ib[0][s] = row[384];
        vb[0][s] = row[256]; kb[0][s] = row[128];
    }
    for (int gidx = 0; gidx < 16; gidx++) {
        const int cb = gidx & 1;
        if (gidx + 1 < 16) {
            const float* gbase = base + (size_t)(gidx + 1) * 4 * 768;
#pragma unroll
            for (int s = 0; s < 4; s++) {
                const float* row = gbase + (size_t)s * 768;
                fb[cb ^ 1][s] = row[512]; ib[cb ^ 1][s] = row[384];
                vb[cb ^ 1][s] = row[256]; kb[cb ^ 1][s] = row[128];
            }
        }
#pragma unroll
        for (int s = 0; s < 4; s++) {
            a += fb[cb][s];
            float u = ib[cb][s] - a;
            pm = fmaxf(pm, u);
            float eu = __expf(u);
            g_PM[oidx] = pm;
            g_Vt[oidx] = vb[cb][s] * eu;
            p = fmaf(kb[cb][s], eu, p);
            g_P[oidx] = p;
            oidx += HH;
        }
    }
    g_aL[(b * NC + c) * HH + j] = a;
}

__global__ __launch_bounds__(128) void n0m0_k()
{
    const int b = blockIdx.x;
    const int j = threadIdx.x;
    float m0 = 0.f, n0 = 0.f;
    for (int c = 0; c < NC; c++) {
        int ci = (b * NC + c) * HH + j;
        g_m0s[ci] = m0;
        g_n0s[ci] = n0;
        size_t li = (size_t)(b * TT + c * LL + (LL - 1)) * HH + j;
        float pml = g_PM[li];
        float pl  = g_P[li];
        float ML = fmaxf(m0, pml);
        n0 = __expf(m0 - ML) * n0 + __expf(-ML) * pl;
        m0 = g_aL[ci] + ML;
    }
}

__global__ __launch_bounds__(256) void gc_k()
{
    float* Vs = dsm;
    float* Ks = dsm + 64 * 128;
    const int b = blockIdx.x >> 4, c = blockIdx.x & 15;
    const int tid = threadIdx.x;
    const float* __restrict__ vb = g_Vt + (size_t)(b * TT + c * LL) * HH;
    const float* __restrict__ pb = g_proj + (size_t)(b * TT + c * LL) * 768;
    for (int i = tid; i < 2048; i += 256) {
        int s = i >> 5, j4 = i & 31;
        ((float4*)Vs)[i] = ((const float4*)vb)[i];
        float4 kv = *(const float4*)(pb + (size_t)s * 768 + 128 + j4 * 4);
        *(float4*)(Ks + s * 132 + j4 * 4) = kv;
    }
    __syncthreads();
    const int r0 = (tid >> 4) * 8, j0 = (tid & 15) * 8;
    float acc[8][8];
#pragma unroll
    for (int i = 0; i < 8; i++)
#pragma unroll
        for (int jj = 0; jj < 8; jj++) acc[i][jj] = 0.f;
    for (int s = 0; s < 64; s++) {
        float4 va = *(float4*)(Vs + s * 128 + r0);
        float4 vb4 = *(float4*)(Vs + s * 128 + r0 + 4);
        float4 ka = *(float4*)(Ks + s * 132 + j0);
        float4 kb = *(float4*)(Ks + s * 132 + j0 + 4);
        float vr[8] = {va.x, va.y, va.z, va.w, vb4.x, vb4.y, vb4.z, vb4.w};
        float kj[8] = {ka.x, ka.y, ka.z, ka.w, kb.x, kb.y, kb.z, kb.w};
#pragma unroll
        for (int i = 0; i < 8; i++)
#pragma unroll
            for (int jj = 0; jj < 8; jj++)
                acc[i][jj] = fmaf(vr[i], kj[jj], acc[i][jj]);
    }
    float* gout = g_Gc + (size_t)(b * NC + c) * (HH * HH);
#pragma unroll
    for (int i = 0; i < 8; i++)
#pragma unroll
        for (int jj = 0; jj < 8; jj += 4) {
            float4 v = {acc[i][jj], acc[i][jj + 1], acc[i][jj + 2], acc[i][jj + 3]};
            *(float4*)(gout + (size_t)(r0 + i) * HH + j0 + jj) = v;
        }
}

__global__ __launch_bounds__(256) void sg_k()
{
    float* Qs = dsm;
    float* KV = dsm + 64 * 128;
    float* Ss = dsm + 64 * 128 + 64 * 132;
    const int b = blockIdx.x >> 4, c = blockIdx.x & 15;
    const int tid = threadIdx.x;
    const float* __restrict__ pb = g_proj + (size_t)(b * TT + c * LL) * 768;
    const float* __restrict__ vb = g_Vt + (size_t)(b * TT + c * LL) * HH;
    for (int i = tid; i < 2048; i += 256) {
        int s = i >> 5, j4 = i & 31;
        *(float4*)(Qs + s * 128 + j4 * 4) = *(const float4*)(pb + (size_t)s * 768 + j4 * 4);
        *(float4*)(KV + s * 132 + j4 * 4) = *(const float4*)(pb + (size_t)s * 768 + 128 + j4 * 4);
    }
    __syncthreads();
    {
        const int t0 = (tid >> 4) * 4, s0 = (tid & 15) * 4;
        float acc[4][4];
#pragma unroll
        for (int i = 0; i < 4; i++)
#pragma unroll
            for (int s = 0; s < 4; s++) acc[i][s] = 0.f;
        for (int jj = 0; jj < 128; jj += 4) {
            float4 q[4], k[4];
#pragma unroll
            for (int i = 0; i < 4; i++) q[i] = *(float4*)(Qs + (t0 + i) * 128 + jj);
#pragma unroll
            for (int s = 0; s < 4; s++) k[s] = *(float4*)(KV + (s0 + s) * 132 + jj);
#pragma unroll
            for (int i = 0; i < 4; i++)
#pragma unroll
                for (int s = 0; s < 4; s++)
                    acc[i][s] += q[i].x * k[s].x + q[i].y * k[s].y
                               + q[i].z * k[s].z + q[i].w * k[s].w;
        }
#pragma unroll
        for (int i = 0; i < 4; i++)
#pragma unroll
            for (int s = 0; s < 4; s++)
                Ss[(t0 + i) * 65 + s0 + s] = (s0 + s <= t0 + i) ? acc[i][s] : 0.f;
    }
    __syncthreads();
    for (int i = tid; i < 2048; i += 256) {
        int s = i >> 5, j4 = i & 31;
        *(float4*)(KV + s * 132 + j4 * 4) = *(const float4*)(vb + (size_t)s * HH + j4 * 4);
    }
    __syncthreads();
    {
        const int t0 = (tid >> 5) * 8, r0 = (tid & 31) * 4;
        float acc[8][4];
#pragma unroll
        for (int i = 0; i < 8; i++)
#pragma unroll
            for (int jj = 0; jj < 4; jj++) acc[i][jj] = 0.f;
        for (int s = 0; s < 64; s++) {
            float4 v = *(float4*)(KV + s * 132 + r0);
#pragma unroll
            for (int i = 0; i < 8; i++) {
                float sv = Ss[(t0 + i) * 65 + s];
                acc[i][0] = fmaf(sv, v.x, acc[i][0]);
                acc[i][1] = fmaf(sv, v.y, acc[i][1]);
                acc[i][2] = fmaf(sv, v.z, acc[i][2]);
                acc[i][3] = fmaf(sv, v.w, acc[i][3]);
            }
        }
        float* gout = g_G + (size_t)(b * TT + c * LL) * HH;
#pragma unroll
        for (int i = 0; i < 8; i++) {
            float4 o4 = {acc[i][0], acc[i][1], acc[i][2], acc[i][3]};
            *(float4*)(gout + (size_t)(t0 + i) * HH + r0) = o4;
        }
    }
}

__global__ __launch_bounds__(256) void cscan_k()
{
    int idx = blockIdx.x * 256 + threadIdx.x;
    int b = idx >> 14;
    int rj = idx & 16383;
    int r = rj >> 7;
    float C = 0.f;
    for (int c = 0; c < NC; c++) {
        size_t so = (size_t)(b * NC + c) * 16384 + rj;
        g_Cst[so] = C;
        float m0 = g_m0s[(b * NC + c) * HH + r];
        float pml = g_PM[(size_t)(b * TT + c * LL + LL - 1) * HH + r];
        float ML = fmaxf(m0, pml);
        C = __expf(m0 - ML) * C + __expf(-ML) * g_Gc[so];
    }
}

// ---- final: h = o * (e^{m0-M} C0 q + e^{-M} G) / den    (den fused in)
__global__ __launch_bounds__(256) void inter_k(float* __restrict__ out)
{
    __shared__ float qs[16][128];
    __shared__ float rden_s[16];
    const int blk = blockIdx.x;
    const int b = blk >> 6;
    const int c = (blk >> 2) & 15;
    const int tb = blk & 3;
    const int tid = threadIdx.x;
    const int r = tid >> 1, half = tid & 1;
    const int t0 = c * LL + tb * 16;

    const float* pb = g_proj + (size_t)(b * TT + t0) * 768;
    for (int i = tid; i < 512; i += 256) {
        int tt = i >> 5, j4 = i & 31;
        *(float4*)(&qs[tt][j4 * 4]) = *(const float4*)(pb + (size_t)tt * 768 + j4 * 4);
    }
    float Creg[64];
    const float* cb = g_Cst + (size_t)(b * NC + c) * 16384 + (size_t)r * 128 + half * 64;
#pragma unroll
    for (int i = 0; i < 16; i++) {
        float4 v = *(const float4*)(cb + i * 4);
        Creg[4 * i] = v.x; Creg[4 * i + 1] = v.y;
        Creg[4 * i + 2] = v.z; Creg[4 * i + 3] = v.w;
    }
    float m0 = g_m0s[(b * NC + c) * HH + r];
    float em0a = __expf(-m0);
    __syncthreads();

    {
        const int tt = tid >> 4, jg = tid & 15, j0 = jg * 8;
        const int ci = (b * NC + c) * HH;
        const size_t gi2 = (size_t)(b * TT + t0 + tt) * HH;
        float d = 0.f;
#pragma unroll
        for (int s = 0; s < 8; s++) {
            int j = j0 + s;
            float m0j = g_m0s[ci + j];
            float pmj = g_PM[gi2 + j];
            float g1 = __expf(fminf(0.f, m0j - pmj));
            float g2 = fminf(__expf(-m0j), __expf(-pmj));
            float nv = g1 * g_n0s[ci + j] + g2 * g_P[gi2 + j];
            d = fmaf(qs[tt][j], nv, d);
        }
        d += __shfl_xor_sync(0xffffffffu, d, 1);
        d += __shfl_xor_sync(0xffffffffu, d, 2);
        d += __shfl_xor_sync(0xffffffffu, d, 4);
        d += __shfl_xor_sync(0xffffffffu, d, 8);
        if (jg == 0) rden_s[tt] = 1.f / fmaxf(fabsf(d), 1.f);
    }
    __syncthreads();

    for (int tt = 0; tt < 16; tt++) {
        float acc = 0.f;
        const float* qrow = &qs[tt][half * 64];
#pragma unroll
        for (int i = 0; i < 16; i++) {
            float4 qv = *(const float4*)(qrow + i * 4);
            acc = fmaf(Creg[4 * i], qv.x, acc);
            acc = fmaf(Creg[4 * i + 1], qv.y, acc);
            acc = fmaf(Creg[4 * i + 2], qv.z, acc);
            acc = fmaf(Creg[4 * i + 3], qv.w, acc);
        }
        acc += __shfl_xor_sync(0xffffffffu, acc, 1);
        if (half == 0) {
            int t = t0 + tt;
            size_t gi = (size_t)(b * TT + t) * HH + r;
            float pm = g_PM[gi];
            float g1 = __expf(fminf(0.f, m0 - pm));
            float g2 = fminf(em0a, __expf(-pm));
            float htl = g1 * acc + g2 * g_G[gi];
            float o = g_proj[(size_t)(b * TT + t) * 768 + 640 + r];
            out[gi] = o * htl * rden_s[tt];
        }
    }
}

// ===========================================================================
extern "C" void kernel_launch(void* const* d_in, const int* in_sizes, int n_in,
                              void* d_out, int out_size)
{
    const float* x  = (const float*)d_in[0];
    const float* sW = (const float*)d_in[1];
    const float* sR = (const float*)d_in[2];
    const float* sb = (const float*)d_in[3];
    const float* Wq = (const float*)d_in[4];
    const float* Wk = (const float*)d_in[5];
    const float* Wv = (const float*)d_in[6];
    const float* Wi = (const float*)d_in[7];
    const float* Wf = (const float*)d_in[8];
    const float* Wo = (const float*)d_in[9];
    const float* bq = (const float*)d_in[10];
    const float* bk = (const float*)d_in[11];
    const float* bv = (const float*)d_in[12];
    const float* bi = (const float*)d_in[13];
    const float* bf = (const float*)d_in[14];
    const float* bo = (const float*)d_in[15];

    const int GC_SMEM = (64 * 128 + 64 * 132) * 4;
    const int SG_SMEM = (64 * 128 + 64 * 132 + 64 * 65) * 4;
    cudaFuncSetAttribute(gc_k, cudaFuncAttributeMaxDynamicSharedMemorySize, GC_SMEM);
    cudaFuncSetAttribute(sg_k, cudaFuncAttributeMaxDynamicSharedMemorySize, SG_SMEM);
    cudaFuncSetAttribute(gemm_k, cudaFuncAttributeMaxDynamicSharedMemorySize, GEMM_SMEM);

    // GEMM1: Wx = x @ sW^T + sb
    GemmArgs a1;
    for (int s = 0; s < 6; s++) {
        int ss = (s < 4) ? s : 3;
        a1.W[s] = sW + (size_t)ss * 128 * 128;
        a1.Bi[s] = sb + (size_t)ss * 128;
        a1.scale[s] = 1.f;
        a1.sigm[s] = 0;
    }
    gemm_k<<<dim3(8, 64), 256, GEMM_SMEM>>>(0, x, a1);

    // sLSTM scan (cluster 4 per batch, st.async exchange)
    slstm_k<<<32, 128>>>(sR);

    // GEMM2: proj = h1 @ [Wq Wk Wv Wi Wf Wo]^T + biases (k scaled, o sigmoided)
    GemmArgs a2;
    const float* Ws2[6] = {Wq, Wk, Wv, Wi, Wf, Wo};
    const float* Bs2[6] = {bq, bk, bv, bi, bf, bo};
    const float inv_sqrt_h = 0.08838834764831845f;
    for (int s = 0; s < 6; s++) {
        a2.W[s] = Ws2[s];
        a2.Bi[s] = Bs2[s];
        a2.scale[s] = (s == 1) ? inv_sqrt_h : 1.f;
        a2.sigm[s] = (s == 5) ? 1 : 0;
    }
    gemm_k<<<dim3(12, 64), 256, GEMM_SMEM>>>(1, nullptr, a2);

    // mLSTM chunkwise pipeline
    prep_k<<<BB * NC, 128>>>();
    gc_k<<<BB * NC, 256, GC_SMEM>>>();
    sg_k<<<BB * NC, 256, SG_SMEM>>>();
    n0m0_k<<<BB, 128>>>();
    cscan_k<<<(BB * HH * HH) / 256, 256>>>();
    inter_k<<<BB * NC * 4, 256>>>((float*)d_out);
}